// round 10
// baseline (speedup 1.0000x reference)
#include <cuda_runtime.h>
#include <cstdint>

#define NNODES  50000
#define NPAD    50048      // 391 * 128
#define NEDGE   500000
#define DIM     128
#define DIM2    256
#define NLAYERS 5
#define NGRAPH  128

// ---------------- scratch (static device globals; zero-initialized) ----------------
__device__ float g_h [(size_t)NPAD * DIM];
__device__ float g_z [(size_t)NPAD * DIM];
__device__ float g_z1[(size_t)NPAD * DIM2];
__device__ float g_sum1[DIM2], g_sq1[DIM2];
__device__ float g_sum2[DIM ], g_sq2[DIM ];
__device__ int   g_cnt1, g_cnt2;            // last-CTA arrival counters

// ---------------- PTX helpers (baseline features only) ----------------
__device__ __forceinline__ void red_add_v4(float* p, float4 v) {
    asm volatile("red.global.add.v4.f32 [%0], {%1, %2, %3, %4};"
                 :: "l"(p), "f"(v.x), "f"(v.y), "f"(v.z), "f"(v.w) : "memory");
}
__device__ __forceinline__ void fma2(unsigned long long& d,
                                     unsigned long long a, unsigned long long b) {
    asm("fma.rn.f32x2 %0, %1, %2, %0;" : "+l"(d) : "l"(a), "l"(b));
}

// ---------------- layer-0 init: h = atom_emb[x]; z = h; zero xpool region ----------------
__global__ void k_init(const int* __restrict__ x, const float* __restrict__ atom_emb,
                       float* __restrict__ out) {
    int i = blockIdx.x * blockDim.x + threadIdx.x;
    if (i < NGRAPH * DIM) out[i] = 0.f;
    if (i >= NNODES * 32) return;
    int n = i >> 5, c = (i & 31) * 4;
    int a = __ldg(x + n);
    float4 v = *(const float4*)(atom_emb + (size_t)a * DIM + c);
    *(float4*)(g_h + (size_t)n * DIM + c) = v;
    *(float4*)(g_z + (size_t)n * DIM + c) = v;
}

// ---------------- message passing: z[dst] += relu(h[src] + bond_emb[attr]) ----------------
// 4 edges per warp for MLP; NEDGE % 32 == 0 so no bounds checks.
__global__ void k_scatter(const int* __restrict__ src, const int* __restrict__ dst,
                          const int* __restrict__ eattr, const float* __restrict__ bond_emb) {
    const int wid  = threadIdx.x >> 5;
    const int lane = threadIdx.x & 31;
    const int e0 = blockIdx.x * 32 + wid * 4;
    const int c4 = lane * 4;

    int s0 = __ldg(src + e0),     s1 = __ldg(src + e0 + 1);
    int s2 = __ldg(src + e0 + 2), s3 = __ldg(src + e0 + 3);
    int a0 = __ldg(eattr + e0),     a1 = __ldg(eattr + e0 + 1);
    int a2 = __ldg(eattr + e0 + 2), a3 = __ldg(eattr + e0 + 3);
    int d0 = __ldg(dst + e0),     d1 = __ldg(dst + e0 + 1);
    int d2 = __ldg(dst + e0 + 2), d3 = __ldg(dst + e0 + 3);

    float4 h0 = *(const float4*)(g_h + (size_t)s0 * DIM + c4);
    float4 h1 = *(const float4*)(g_h + (size_t)s1 * DIM + c4);
    float4 h2 = *(const float4*)(g_h + (size_t)s2 * DIM + c4);
    float4 h3 = *(const float4*)(g_h + (size_t)s3 * DIM + c4);
    float4 e0v = *(const float4*)(bond_emb + (size_t)a0 * DIM + c4);
    float4 e1v = *(const float4*)(bond_emb + (size_t)a1 * DIM + c4);
    float4 e2v = *(const float4*)(bond_emb + (size_t)a2 * DIM + c4);
    float4 e3v = *(const float4*)(bond_emb + (size_t)a3 * DIM + c4);

    float4 m;
    m.x = fmaxf(h0.x + e0v.x, 0.f); m.y = fmaxf(h0.y + e0v.y, 0.f);
    m.z = fmaxf(h0.z + e0v.z, 0.f); m.w = fmaxf(h0.w + e0v.w, 0.f);
    red_add_v4(g_z + (size_t)d0 * DIM + c4, m);
    m.x = fmaxf(h1.x + e1v.x, 0.f); m.y = fmaxf(h1.y + e1v.y, 0.f);
    m.z = fmaxf(h1.z + e1v.z, 0.f); m.w = fmaxf(h1.w + e1v.w, 0.f);
    red_add_v4(g_z + (size_t)d1 * DIM + c4, m);
    m.x = fmaxf(h2.x + e2v.x, 0.f); m.y = fmaxf(h2.y + e2v.y, 0.f);
    m.z = fmaxf(h2.z + e2v.z, 0.f); m.w = fmaxf(h2.w + e2v.w, 0.f);
    red_add_v4(g_z + (size_t)d2 * DIM + c4, m);
    m.x = fmaxf(h3.x + e3v.x, 0.f); m.y = fmaxf(h3.y + e3v.y, 0.f);
    m.z = fmaxf(h3.z + e3v.z, 0.f); m.w = fmaxf(h3.w + e3v.w, 0.f);
    red_add_v4(g_z + (size_t)d3 * DIM + c4, m);
}

// ---------------- SGEMM via packed FFMA2, B pre-packed in smem ----------------
// C[NPAD x NC] = A[NPAD x K] @ Bw[K x NC] + bias
// BM=128, BN=64, BK=16, 256 threads, 8x4 microtile.
// Accumulators acc2[mp][n]: f32x2 pairs over adjacent M rows (free from float4 LDS of
// transposed As). B values stored in smem ALREADY broadcast-packed ({v,v} u64 pairs),
// so the inner loop is 4 LDS.128 + 16 FFMA2 per kk — zero pack instructions.
// Packed B row layout (128 floats + 4 pad): columns n=4t..4t+3 ->
//   {v(4t),v(4t)},{v(4t+1),v(4t+1)} at float offset t*4, and
//   {v(4t+2),..},{v(4t+3),..}       at float offset 64 + t*4.
// Both fragment LDS.128 are contiguous 256B per 16 lanes -> conflict-free.
// If AFF: BN affine computed inline from stats; last CTA re-zeroes stats (replay safe).
// smem floats: As[2][16][132] @0 (4224) | Bs2[2][16][132] @4224 (4224) | saff @8448 (512)
template<int K, int NC, bool AFF>
__global__ void __launch_bounds__(256, 3)
k_gemm(const float* __restrict__ A, const float* __restrict__ Bw,
       const float* __restrict__ bias,
       const float* __restrict__ sumA, const float* __restrict__ sqA,
       const float* __restrict__ gammaA, const float* __restrict__ betaA,
       int* __restrict__ cntA, int nCTA,
       float* __restrict__ C, float* __restrict__ gsum, float* __restrict__ gsq) {
    __shared__ float smem[4224 + 4224 + 512];
    __shared__ int s_last;
    float* saff = smem + 8448;

    const int tid = threadIdx.x;
    const int tx  = tid & 15, ty = tid >> 4;
    const int bm0 = blockIdx.x * 128, bn0 = blockIdx.y * 64;

    const int a_row = tid >> 2;
    const int a_c4  = (tid & 3) * 4;
    const int b_row = tid >> 4;              // 0..15
    const int b_t   = tid & 15;              // column group t: cols 4t..4t+3

    if (AFF) {
        if (tid < K) {
            const float invn = 1.0f / (float)NNODES;
            float mu  = sumA[tid] * invn;
            float var = fmaxf(sqA[tid] * invn - mu * mu, 0.f);
            float sc  = rsqrtf(var + 1e-5f) * gammaA[tid];
            saff[tid]     = sc;
            saff[K + tid] = betaA[tid] - mu * sc;
        }
        __syncthreads();
        if (tid == 0) {
            __threadfence();
            int old = atomicAdd(cntA, 1);
            s_last = (old == nCTA - 1);
        }
        __syncthreads();
        if (s_last) {
            if (tid < K) { ((float*)sumA)[tid] = 0.f; ((float*)sqA)[tid] = 0.f; }
            if (tid == 0) *cntA = 0;
        }
    }

    unsigned long long acc2[4][4];    // [m-pair][n]; lo = even row of pair
    #pragma unroll
    for (int mp = 0; mp < 4; mp++)
        #pragma unroll
        for (int n = 0; n < 4; n++) acc2[mp][n] = 0ULL;

    const float* Abase = A  + (size_t)(bm0 + a_row) * K + a_c4;
    const float* Bbase = Bw + (size_t)b_row * NC + bn0 + b_t * 4;

    float4 pa0, pa1, pb0;
    pa0 = *(const float4*)(Abase);
    pa1 = *(const float4*)(Abase + (size_t)64 * K);
    pb0 = *(const float4*)(Bbase);

    #pragma unroll 1
    for (int k0 = 0; k0 < K; k0 += 16) {
        const bool nxt = (k0 + 16) < K;
        {
            const int buf = (k0 >> 4) & 1;
            if (AFF) {
                const float* sc = saff + k0 + a_c4;
                const float* sh = sc + K;
                pa0.x = fmaxf(fmaf(pa0.x, sc[0], sh[0]), 0.f);
                pa0.y = fmaxf(fmaf(pa0.y, sc[1], sh[1]), 0.f);
                pa0.z = fmaxf(fmaf(pa0.z, sc[2], sh[2]), 0.f);
                pa0.w = fmaxf(fmaf(pa0.w, sc[3], sh[3]), 0.f);
                pa1.x = fmaxf(fmaf(pa1.x, sc[0], sh[0]), 0.f);
                pa1.y = fmaxf(fmaf(pa1.y, sc[1], sh[1]), 0.f);
                pa1.z = fmaxf(fmaf(pa1.z, sc[2], sh[2]), 0.f);
                pa1.w = fmaxf(fmaf(pa1.w, sc[3], sh[3]), 0.f);
            }
            float* as = smem + buf * 2112;
            as[(a_c4 + 0) * 132 + a_row] = pa0.x;
            as[(a_c4 + 1) * 132 + a_row] = pa0.y;
            as[(a_c4 + 2) * 132 + a_row] = pa0.z;
            as[(a_c4 + 3) * 132 + a_row] = pa0.w;
            as[(a_c4 + 0) * 132 + a_row + 64] = pa1.x;
            as[(a_c4 + 1) * 132 + a_row + 64] = pa1.y;
            as[(a_c4 + 2) * 132 + a_row + 64] = pa1.z;
            as[(a_c4 + 3) * 132 + a_row + 64] = pa1.w;
            // pre-packed B: duplicate each value into a u64 pair at staging time
            float* bs = smem + 4224 + buf * 2112;
            float4 q0 = make_float4(pb0.x, pb0.x, pb0.y, pb0.y);
            float4 q1 = make_float4(pb0.z, pb0.z, pb0.w, pb0.w);
            *(float4*)(bs + b_row * 132 + b_t * 4)      = q0;
            *(float4*)(bs + b_row * 132 + 64 + b_t * 4) = q1;
        }
        __syncthreads();

        if (nxt) {
            pa0 = *(const float4*)(Abase + k0 + 16);
            pa1 = *(const float4*)(Abase + (size_t)64 * K + k0 + 16);
            pb0 = *(const float4*)(Bbase + (size_t)(k0 + 16) * NC);
        }

        {
            const int buf = (k0 >> 4) & 1;
            const float* as = smem + buf * 2112;
            const float* bs = smem + 4224 + buf * 2112;
            #pragma unroll
            for (int kk = 0; kk < 16; kk++) {
                unsigned long long am[4];            // m-pairs, free from float4 loads
                unsigned long long bp[4];            // pre-packed n broadcasts
                *(float4*)&am[0] = *(const float4*)(as + kk * 132 + ty * 8);
                *(float4*)&am[2] = *(const float4*)(as + kk * 132 + ty * 8 + 4);
                *(float4*)&bp[0] = *(const float4*)(bs + kk * 132 + tx * 4);
                *(float4*)&bp[2] = *(const float4*)(bs + kk * 132 + 64 + tx * 4);
                #pragma unroll
                for (int mp = 0; mp < 4; mp++) {
                    fma2(acc2[mp][0], am[mp], bp[0]);
                    fma2(acc2[mp][1], am[mp], bp[1]);
                    fma2(acc2[mp][2], am[mp], bp[2]);
                    fma2(acc2[mp][3], am[mp], bp[3]);
                }
            }
        }
    }

    // epilogue: bias add, store, masked per-column stats
    float4 bvq = *(const float4*)(bias + bn0 + tx * 4);
    float psum[4] = {0.f, 0.f, 0.f, 0.f}, psq[4] = {0.f, 0.f, 0.f, 0.f};
    #pragma unroll
    for (int m = 0; m < 8; m++) {
        const int mp = m >> 1, par = m & 1;
        int row = bm0 + ty * 8 + m;
        float4 v;
        v.x = ((const float*)&acc2[mp][0])[par] + bvq.x;
        v.y = ((const float*)&acc2[mp][1])[par] + bvq.y;
        v.z = ((const float*)&acc2[mp][2])[par] + bvq.z;
        v.w = ((const float*)&acc2[mp][3])[par] + bvq.w;
        *(float4*)(C + (size_t)row * NC + bn0 + tx * 4) = v;
        if (row < NNODES) {
            psum[0] += v.x; psq[0] += v.x * v.x;
            psum[1] += v.y; psq[1] += v.y * v.y;
            psum[2] += v.z; psq[2] += v.z * v.z;
            psum[3] += v.w; psq[3] += v.w * v.w;
        }
    }

    __syncthreads();
    float* ssum = smem;                    // [16][64]
    float* ssq  = smem + 1024;             // [16][64]
    #pragma unroll
    for (int n = 0; n < 4; n++) {
        ssum[ty * 64 + tx * 4 + n] = psum[n];
        ssq [ty * 64 + tx * 4 + n] = psq[n];
    }
    __syncthreads();
    if (tid < 64) {
        float s = 0.f, q = 0.f;
        #pragma unroll
        for (int i = 0; i < 16; i++) { s += ssum[i * 64 + tid]; q += ssq[i * 64 + tid]; }
        atomicAdd(gsum + bn0 + tid, s);
        atomicAdd(gsq  + bn0 + tid, q);
    }
}

// ---------------- apply BN2 (+optional ReLU): h = bn(z2); z = h ----------------
__global__ void k_bnapply(const float* __restrict__ gamma, const float* __restrict__ beta,
                          int relu, int nBLK) {
    __shared__ float saff[2 * DIM];
    __shared__ int s_last;
    int tid = threadIdx.x;
    if (tid < DIM) {
        const float invn = 1.0f / (float)NNODES;
        float mu  = g_sum2[tid] * invn;
        float var = fmaxf(g_sq2[tid] * invn - mu * mu, 0.f);
        float sc  = rsqrtf(var + 1e-5f) * gamma[tid];
        saff[tid]       = sc;
        saff[DIM + tid] = beta[tid] - mu * sc;
    }
    __syncthreads();
    if (tid == 0) {
        __threadfence();
        int old = atomicAdd(&g_cnt2, 1);
        s_last = (old == nBLK - 1);
    }
    __syncthreads();
    if (s_last) {
        if (tid < DIM) { g_sum2[tid] = 0.f; g_sq2[tid] = 0.f; }
        if (tid == 0) g_cnt2 = 0;
    }

    int i = blockIdx.x * blockDim.x + tid;
    if (i >= NNODES * 32) return;
    int n = i >> 5, c = (i & 31) * 4;
    float4 v  = *(const float4*)(g_z + (size_t)n * DIM + c);
    float4 sc = *(const float4*)(saff + c);
    float4 sh = *(const float4*)(saff + DIM + c);
    v.x = fmaf(v.x, sc.x, sh.x);
    v.y = fmaf(v.y, sc.y, sh.y);
    v.z = fmaf(v.z, sc.z, sh.z);
    v.w = fmaf(v.w, sc.w, sh.w);
    if (relu) {
        v.x = fmaxf(v.x, 0.f); v.y = fmaxf(v.y, 0.f);
        v.z = fmaxf(v.z, 0.f); v.w = fmaxf(v.w, 0.f);
    }
    *(float4*)(g_h + (size_t)n * DIM + c) = v;
    *(float4*)(g_z + (size_t)n * DIM + c) = v;
}

__global__ void k_pool(const int* __restrict__ batch, float* __restrict__ out) {
    int i = blockIdx.x * blockDim.x + threadIdx.x;
    if (i >= NNODES * 32) return;
    int n = i >> 5, c = (i & 31) * 4;
    float4 v = *(const float4*)(g_h + (size_t)n * DIM + c);
    *(float4*)(out + (size_t)NGRAPH * DIM + (size_t)n * DIM + c) = v;
    int b = __ldg(batch + n);
    red_add_v4(out + (size_t)b * DIM + c, v);
}

// ---------------- launch ----------------
extern "C" void kernel_launch(void* const* d_in, const int* in_sizes, int n_in,
                              void* d_out, int out_size) {
    const int*   batch    = (const int*)  d_in[0];
    const int*   x        = (const int*)  d_in[1];
    const int*   eidx     = (const int*)  d_in[2];
    const int*   eattr    = (const int*)  d_in[3];
    const float* atom_emb = (const float*)d_in[4];
    const float* bond_emb = (const float*)d_in[5];
    const float* W1       = (const float*)d_in[6];
    const float* b1       = (const float*)d_in[7];
    const float* g1       = (const float*)d_in[8];
    const float* be1      = (const float*)d_in[9];
    const float* W2       = (const float*)d_in[10];
    const float* b2       = (const float*)d_in[11];
    const float* gbn      = (const float*)d_in[12];
    const float* bbn      = (const float*)d_in[13];
    float* out = (float*)d_out;

    float *p_z, *p_z1, *p_sum1, *p_sq1, *p_sum2, *p_sq2;
    int *p_cnt1;
    cudaGetSymbolAddress((void**)&p_z,    g_z);
    cudaGetSymbolAddress((void**)&p_z1,   g_z1);
    cudaGetSymbolAddress((void**)&p_sum1, g_sum1);
    cudaGetSymbolAddress((void**)&p_sq1,  g_sq1);
    cudaGetSymbolAddress((void**)&p_sum2, g_sum2);
    cudaGetSymbolAddress((void**)&p_sq2,  g_sq2);
    cudaGetSymbolAddress((void**)&p_cnt1, g_cnt1);

    const int* src = eidx;
    const int* dst = eidx + NEDGE;
    const int ELEM_GRID = (NNODES * 32 + 255) / 256;
    const int G2_CTAS   = (NPAD / 128) * (DIM / 64);

    k_init<<<ELEM_GRID, 256>>>(x, atom_emb, out);

    for (int i = 0; i < NLAYERS; i++) {
        k_scatter<<<NEDGE / 32, 256>>>(src, dst, eattr, bond_emb);
        k_gemm<DIM, DIM2, false><<<dim3(NPAD / 128, DIM2 / 64), 256>>>(
            p_z, W1 + (size_t)i * DIM * DIM2, b1 + (size_t)i * DIM2,
            nullptr, nullptr, nullptr, nullptr, nullptr, 0,
            p_z1, p_sum1, p_sq1);
        k_gemm<DIM2, DIM, true><<<dim3(NPAD / 128, DIM / 64), 256>>>(
            p_z1, W2 + (size_t)i * DIM2 * DIM, b2 + (size_t)i * DIM,
            p_sum1, p_sq1, g1 + (size_t)i * DIM2, be1 + (size_t)i * DIM2,
            p_cnt1, G2_CTAS,
            p_z, p_sum2, p_sq2);
        k_bnapply<<<ELEM_GRID, 256>>>(gbn + (size_t)i * DIM, bbn + (size_t)i * DIM,
                                      i < NLAYERS - 1 ? 1 : 0, ELEM_GRID);
    }

    k_pool<<<ELEM_GRID, 256>>>(batch, out);
}

// round 11
// speedup vs baseline: 1.1950x; 1.1950x over previous
#include <cuda_runtime.h>
#include <cstdint>

#define NNODES  50000
#define NPAD    50048      // 391 * 128
#define NEDGE   500000
#define DIM     128
#define DIM2    256
#define NLAYERS 5
#define NGRAPH  128

// ---------------- scratch (static device globals; zero-initialized) ----------------
__device__ float g_h [(size_t)NPAD * DIM];
__device__ float g_z [(size_t)NPAD * DIM];
__device__ float g_z1[(size_t)NPAD * DIM2];
__device__ float g_sum1[DIM2], g_sq1[DIM2];
__device__ float g_sum2[DIM ], g_sq2[DIM ];
__device__ int   g_cnt1, g_cnt2;            // last-CTA arrival counters

// ---------------- PTX helpers (baseline features only) ----------------
__device__ __forceinline__ void red_add_v4(float* p, float4 v) {
    asm volatile("red.global.add.v4.f32 [%0], {%1, %2, %3, %4};"
                 :: "l"(p), "f"(v.x), "f"(v.y), "f"(v.z), "f"(v.w) : "memory");
}
__device__ __forceinline__ unsigned long long pack2(float x) {
    unsigned long long r;
    asm("mov.b64 %0, {%1, %1};" : "=l"(r) : "r"(__float_as_uint(x)));
    return r;
}
__device__ __forceinline__ void fma2(unsigned long long& d,
                                     unsigned long long a, unsigned long long b) {
    asm("fma.rn.f32x2 %0, %1, %2, %0;" : "+l"(d) : "l"(a), "l"(b));
}

// ---------------- layer-0 init: h = atom_emb[x]; z = h; zero xpool region ----------------
__global__ void k_init(const int* __restrict__ x, const float* __restrict__ atom_emb,
                       float* __restrict__ out) {
    int i = blockIdx.x * blockDim.x + threadIdx.x;
    if (i < NGRAPH * DIM) out[i] = 0.f;
    if (i >= NNODES * 32) return;
    int n = i >> 5, c = (i & 31) * 4;
    int a = __ldg(x + n);
    float4 v = *(const float4*)(atom_emb + (size_t)a * DIM + c);
    *(float4*)(g_h + (size_t)n * DIM + c) = v;
    *(float4*)(g_z + (size_t)n * DIM + c) = v;
}

// ---------------- message passing: z[dst] += relu(h[src] + bond_emb[attr]) ----------------
// 8 edges per warp for deep MLP; all 16 gathers issued before any reduction.
__global__ void k_scatter(const int* __restrict__ src, const int* __restrict__ dst,
                          const int* __restrict__ eattr, const float* __restrict__ bond_emb) {
    const int wid  = threadIdx.x >> 5;
    const int lane = threadIdx.x & 31;
    const int e0 = blockIdx.x * 64 + wid * 8;
    const int c4 = lane * 4;

    if (e0 + 8 <= NEDGE) {
        int s[8], d[8], a[8];
        #pragma unroll
        for (int j = 0; j < 8; j++) {
            s[j] = __ldg(src + e0 + j);
            d[j] = __ldg(dst + e0 + j);
            a[j] = __ldg(eattr + e0 + j);
        }
        float4 hv[8], ev[8];
        #pragma unroll
        for (int j = 0; j < 8; j++)
            hv[j] = *(const float4*)(g_h + (size_t)s[j] * DIM + c4);
        #pragma unroll
        for (int j = 0; j < 8; j++)
            ev[j] = *(const float4*)(bond_emb + (size_t)a[j] * DIM + c4);
        #pragma unroll
        for (int j = 0; j < 8; j++) {
            float4 m;
            m.x = fmaxf(hv[j].x + ev[j].x, 0.f);
            m.y = fmaxf(hv[j].y + ev[j].y, 0.f);
            m.z = fmaxf(hv[j].z + ev[j].z, 0.f);
            m.w = fmaxf(hv[j].w + ev[j].w, 0.f);
            red_add_v4(g_z + (size_t)d[j] * DIM + c4, m);
        }
    } else {
        for (int j = 0; j < 8; j++) {
            int e = e0 + j;
            if (e >= NEDGE) break;
            int s = __ldg(src + e), d = __ldg(dst + e), a = __ldg(eattr + e);
            float4 hv = *(const float4*)(g_h + (size_t)s * DIM + c4);
            float4 ev = *(const float4*)(bond_emb + (size_t)a * DIM + c4);
            float4 m;
            m.x = fmaxf(hv.x + ev.x, 0.f);
            m.y = fmaxf(hv.y + ev.y, 0.f);
            m.z = fmaxf(hv.z + ev.z, 0.f);
            m.w = fmaxf(hv.w + ev.w, 0.f);
            red_add_v4(g_z + (size_t)d * DIM + c4, m);
        }
    }
}

// ---------------- SGEMM via packed FFMA2 (m-paired accumulators) — R9 design ----------------
// C[NPAD x NC] = A[NPAD x K] @ Bw[K x NC] + bias
// BM=128, BN=64, BK=16, 256 threads, 8x4 microtile.
// Accumulators acc2[mp][n]: u64 f32x2 pair over adjacent M rows (free from float4 LDS
// of transposed As); B values broadcast-packed in registers (4 pack2/kk).
// If AFF: BN affine computed inline from stats; last CTA re-zeroes stats (replay safe).
// smem floats: As[2][16][132] @0 (4224) | Bs[2][16][64] @4224 (2048) | saff @6272 (512)
template<int K, int NC, bool AFF>
__global__ void __launch_bounds__(256, 3)
k_gemm(const float* __restrict__ A, const float* __restrict__ Bw,
       const float* __restrict__ bias,
       const float* __restrict__ sumA, const float* __restrict__ sqA,
       const float* __restrict__ gammaA, const float* __restrict__ betaA,
       int* __restrict__ cntA, int nCTA,
       float* __restrict__ C, float* __restrict__ gsum, float* __restrict__ gsq) {
    __shared__ float smem[4224 + 2048 + 512];
    __shared__ int s_last;
    float* saff = smem + 6272;

    const int tid = threadIdx.x;
    const int tx  = tid & 15, ty = tid >> 4;
    const int bm0 = blockIdx.x * 128, bn0 = blockIdx.y * 64;

    const int a_row = tid >> 2;
    const int a_c4  = (tid & 3) * 4;
    const int b_row = tid >> 4;
    const int b_c   = (tid & 15) * 4;

    if (AFF) {
        if (tid < K) {
            const float invn = 1.0f / (float)NNODES;
            float mu  = sumA[tid] * invn;
            float var = fmaxf(sqA[tid] * invn - mu * mu, 0.f);
            float sc  = rsqrtf(var + 1e-5f) * gammaA[tid];
            saff[tid]     = sc;
            saff[K + tid] = betaA[tid] - mu * sc;
        }
        __syncthreads();
        if (tid == 0) {
            __threadfence();
            int old = atomicAdd(cntA, 1);
            s_last = (old == nCTA - 1);
        }
        __syncthreads();
        if (s_last) {
            if (tid < K) { ((float*)sumA)[tid] = 0.f; ((float*)sqA)[tid] = 0.f; }
            if (tid == 0) *cntA = 0;
        }
    }

    unsigned long long acc2[4][4];    // [m-pair][n]; lo = even row of pair
    #pragma unroll
    for (int mp = 0; mp < 4; mp++)
        #pragma unroll
        for (int n = 0; n < 4; n++) acc2[mp][n] = 0ULL;

    const float* Abase = A  + (size_t)(bm0 + a_row) * K + a_c4;
    const float* Bbase = Bw + (size_t)b_row * NC + bn0 + b_c;

    float4 pa0, pa1, pb0;
    pa0 = *(const float4*)(Abase);
    pa1 = *(const float4*)(Abase + (size_t)64 * K);
    pb0 = *(const float4*)(Bbase);

    #pragma unroll 1
    for (int k0 = 0; k0 < K; k0 += 16) {
        const bool nxt = (k0 + 16) < K;
        {
            const int buf = (k0 >> 4) & 1;
            if (AFF) {
                const float* sc = saff + k0 + a_c4;
                const float* sh = sc + K;
                pa0.x = fmaxf(fmaf(pa0.x, sc[0], sh[0]), 0.f);
                pa0.y = fmaxf(fmaf(pa0.y, sc[1], sh[1]), 0.f);
                pa0.z = fmaxf(fmaf(pa0.z, sc[2], sh[2]), 0.f);
                pa0.w = fmaxf(fmaf(pa0.w, sc[3], sh[3]), 0.f);
                pa1.x = fmaxf(fmaf(pa1.x, sc[0], sh[0]), 0.f);
                pa1.y = fmaxf(fmaf(pa1.y, sc[1], sh[1]), 0.f);
                pa1.z = fmaxf(fmaf(pa1.z, sc[2], sh[2]), 0.f);
                pa1.w = fmaxf(fmaf(pa1.w, sc[3], sh[3]), 0.f);
            }
            float* as = smem + buf * 2112;
            as[(a_c4 + 0) * 132 + a_row] = pa0.x;
            as[(a_c4 + 1) * 132 + a_row] = pa0.y;
            as[(a_c4 + 2) * 132 + a_row] = pa0.z;
            as[(a_c4 + 3) * 132 + a_row] = pa0.w;
            as[(a_c4 + 0) * 132 + a_row + 64] = pa1.x;
            as[(a_c4 + 1) * 132 + a_row + 64] = pa1.y;
            as[(a_c4 + 2) * 132 + a_row + 64] = pa1.z;
            as[(a_c4 + 3) * 132 + a_row + 64] = pa1.w;
            float* bs = smem + 4224 + buf * 1024;
            *(float4*)(bs + b_row * 64 + b_c) = pb0;
        }
        __syncthreads();

        if (nxt) {
            pa0 = *(const float4*)(Abase + k0 + 16);
            pa1 = *(const float4*)(Abase + (size_t)64 * K + k0 + 16);
            pb0 = *(const float4*)(Bbase + (size_t)(k0 + 16) * NC);
        }

        {
            const int buf = (k0 >> 4) & 1;
            const float* as = smem + buf * 2112;
            const float* bs = smem + 4224 + buf * 1024;
            #pragma unroll
            for (int kk = 0; kk < 16; kk++) {
                unsigned long long am[4];
                float br[4];
                *(float4*)&am[0] = *(const float4*)(as + kk * 132 + ty * 8);
                *(float4*)&am[2] = *(const float4*)(as + kk * 132 + ty * 8 + 4);
                *(float4*)&br[0] = *(const float4*)(bs + kk * 64 + tx * 4);
                unsigned long long bp0 = pack2(br[0]);
                unsigned long long bp1 = pack2(br[1]);
                unsigned long long bp2 = pack2(br[2]);
                unsigned long long bp3 = pack2(br[3]);
                #pragma unroll
                for (int mp = 0; mp < 4; mp++) {
                    fma2(acc2[mp][0], am[mp], bp0);
                    fma2(acc2[mp][1], am[mp], bp1);
                    fma2(acc2[mp][2], am[mp], bp2);
                    fma2(acc2[mp][3], am[mp], bp3);
                }
            }
        }
    }

    // epilogue: bias add, store, masked per-column stats
    float4 bvq = *(const float4*)(bias + bn0 + tx * 4);
    float psum[4] = {0.f, 0.f, 0.f, 0.f}, psq[4] = {0.f, 0.f, 0.f, 0.f};
    #pragma unroll
    for (int m = 0; m < 8; m++) {
        const int mp = m >> 1, par = m & 1;
        int row = bm0 + ty * 8 + m;
        float4 v;
        v.x = ((const float*)&acc2[mp][0])[par] + bvq.x;
        v.y = ((const float*)&acc2[mp][1])[par] + bvq.y;
        v.z = ((const float*)&acc2[mp][2])[par] + bvq.z;
        v.w = ((const float*)&acc2[mp][3])[par] + bvq.w;
        *(float4*)(C + (size_t)row * NC + bn0 + tx * 4) = v;
        if (row < NNODES) {
            psum[0] += v.x; psq[0] += v.x * v.x;
            psum[1] += v.y; psq[1] += v.y * v.y;
            psum[2] += v.z; psq[2] += v.z * v.z;
            psum[3] += v.w; psq[3] += v.w * v.w;
        }
    }

    __syncthreads();
    float* ssum = smem;                    // [16][64]
    float* ssq  = smem + 1024;             // [16][64]
    #pragma unroll
    for (int n = 0; n < 4; n++) {
        ssum[ty * 64 + tx * 4 + n] = psum[n];
        ssq [ty * 64 + tx * 4 + n] = psq[n];
    }
    __syncthreads();
    if (tid < 64) {
        float s = 0.f, q = 0.f;
        #pragma unroll
        for (int i = 0; i < 16; i++) { s += ssum[i * 64 + tid]; q += ssq[i * 64 + tid]; }
        atomicAdd(gsum + bn0 + tid, s);
        atomicAdd(gsq  + bn0 + tid, q);
    }
}

// ---------------- apply BN2 (+optional ReLU): h = bn(z2); z = h ----------------
__global__ void k_bnapply(const float* __restrict__ gamma, const float* __restrict__ beta,
                          int relu, int nBLK) {
    __shared__ float saff[2 * DIM];
    __shared__ int s_last;
    int tid = threadIdx.x;
    if (tid < DIM) {
        const float invn = 1.0f / (float)NNODES;
        float mu  = g_sum2[tid] * invn;
        float var = fmaxf(g_sq2[tid] * invn - mu * mu, 0.f);
        float sc  = rsqrtf(var + 1e-5f) * gamma[tid];
        saff[tid]       = sc;
        saff[DIM + tid] = beta[tid] - mu * sc;
    }
    __syncthreads();
    if (tid == 0) {
        __threadfence();
        int old = atomicAdd(&g_cnt2, 1);
        s_last = (old == nBLK - 1);
    }
    __syncthreads();
    if (s_last) {
        if (tid < DIM) { g_sum2[tid] = 0.f; g_sq2[tid] = 0.f; }
        if (tid == 0) g_cnt2 = 0;
    }

    int i = blockIdx.x * blockDim.x + tid;
    if (i >= NNODES * 32) return;
    int n = i >> 5, c = (i & 31) * 4;
    float4 v  = *(const float4*)(g_z + (size_t)n * DIM + c);
    float4 sc = *(const float4*)(saff + c);
    float4 sh = *(const float4*)(saff + DIM + c);
    v.x = fmaf(v.x, sc.x, sh.x);
    v.y = fmaf(v.y, sc.y, sh.y);
    v.z = fmaf(v.z, sc.z, sh.z);
    v.w = fmaf(v.w, sc.w, sh.w);
    if (relu) {
        v.x = fmaxf(v.x, 0.f); v.y = fmaxf(v.y, 0.f);
        v.z = fmaxf(v.z, 0.f); v.w = fmaxf(v.w, 0.f);
    }
    *(float4*)(g_h + (size_t)n * DIM + c) = v;
    *(float4*)(g_z + (size_t)n * DIM + c) = v;
}

__global__ void k_pool(const int* __restrict__ batch, float* __restrict__ out) {
    int i = blockIdx.x * blockDim.x + threadIdx.x;
    if (i >= NNODES * 32) return;
    int n = i >> 5, c = (i & 31) * 4;
    float4 v = *(const float4*)(g_h + (size_t)n * DIM + c);
    *(float4*)(out + (size_t)NGRAPH * DIM + (size_t)n * DIM + c) = v;
    int b = __ldg(batch + n);
    red_add_v4(out + (size_t)b * DIM + c, v);
}

// ---------------- launch ----------------
extern "C" void kernel_launch(void* const* d_in, const int* in_sizes, int n_in,
                              void* d_out, int out_size) {
    const int*   batch    = (const int*)  d_in[0];
    const int*   x        = (const int*)  d_in[1];
    const int*   eidx     = (const int*)  d_in[2];
    const int*   eattr    = (const int*)  d_in[3];
    const float* atom_emb = (const float*)d_in[4];
    const float* bond_emb = (const float*)d_in[5];
    const float* W1       = (const float*)d_in[6];
    const float* b1       = (const float*)d_in[7];
    const float* g1       = (const float*)d_in[8];
    const float* be1      = (const float*)d_in[9];
    const float* W2       = (const float*)d_in[10];
    const float* b2       = (const float*)d_in[11];
    const float* gbn      = (const float*)d_in[12];
    const float* bbn      = (const float*)d_in[13];
    float* out = (float*)d_out;

    float *p_z, *p_z1, *p_sum1, *p_sq1, *p_sum2, *p_sq2;
    int *p_cnt1;
    cudaGetSymbolAddress((void**)&p_z,    g_z);
    cudaGetSymbolAddress((void**)&p_z1,   g_z1);
    cudaGetSymbolAddress((void**)&p_sum1, g_sum1);
    cudaGetSymbolAddress((void**)&p_sq1,  g_sq1);
    cudaGetSymbolAddress((void**)&p_sum2, g_sum2);
    cudaGetSymbolAddress((void**)&p_sq2,  g_sq2);
    cudaGetSymbolAddress((void**)&p_cnt1, g_cnt1);

    const int* src = eidx;
    const int* dst = eidx + NEDGE;
    const int ELEM_GRID = (NNODES * 32 + 255) / 256;
    const int G2_CTAS   = (NPAD / 128) * (DIM / 64);

    k_init<<<ELEM_GRID, 256>>>(x, atom_emb, out);

    for (int i = 0; i < NLAYERS; i++) {
        k_scatter<<<(NEDGE + 63) / 64, 256>>>(src, dst, eattr, bond_emb);
        k_gemm<DIM, DIM2, false><<<dim3(NPAD / 128, DIM2 / 64), 256>>>(
            p_z, W1 + (size_t)i * DIM * DIM2, b1 + (size_t)i * DIM2,
            nullptr, nullptr, nullptr, nullptr, nullptr, 0,
            p_z1, p_sum1, p_sq1);
        k_gemm<DIM2, DIM, true><<<dim3(NPAD / 128, DIM / 64), 256>>>(
            p_z1, W2 + (size_t)i * DIM2 * DIM, b2 + (size_t)i * DIM,
            p_sum1, p_sq1, g1 + (size_t)i * DIM2, be1 + (size_t)i * DIM2,
            p_cnt1, G2_CTAS,
            p_z, p_sum2, p_sq2);
        k_bnapply<<<ELEM_GRID, 256>>>(gbn + (size_t)i * DIM, bbn + (size_t)i * DIM,
                                      i < NLAYERS - 1 ? 1 : 0, ELEM_GRID);
    }

    k_pool<<<ELEM_GRID, 256>>>(batch, out);
}